// round 16
// baseline (speedup 1.0000x reference)
#include <cuda_runtime.h>

// ---------------- scratch ----------------
__device__ __align__(16) float g_wT[13200000];
__device__ __align__(16) float g_bias[9216];
__device__ __align__(16) float g_h1[13107200];   // 100x32x32x128 NHWC
__device__ __align__(16) float g_h2[6553600];    // 100x16x16x256
__device__ __align__(16) float g_h3[6553600];    // 100x8x8x1024
__device__ __align__(16) float g_h4[1638400];    // 100x4x4x1024
__device__ __align__(16) float g_part[20000000]; // split-K partials
__device__ __align__(16) float g_R[80000];
__device__ __align__(16) float g_tab[800];
__device__ __align__(16) float g_mean[4096];
__device__ __align__(16) float g_invstd[4096];
__device__ __align__(16) float g_bnsum[4096];
__device__ __align__(16) float g_bnss[4096];
__device__ __align__(16) float g_d0[921600];     // 100x3x3x1024 NHWC
__device__ __align__(16) float g_t1[1280000];    // 100x5x5x512
__device__ __align__(16) float g_t2[3097600];    // 100x11x11x256
__device__ __align__(16) float g_t3[6771200];    // 100x23x23x128
__device__ __align__(16) float g_t4[14137600];   // 100x47x47x64

// ---------------- helpers ----------------
__device__ __forceinline__ unsigned long long pack2(float v) {
    unsigned long long r; asm("mov.b64 %0, {%1, %1};" : "=l"(r) : "f"(v)); return r;
}
__device__ __forceinline__ void fma2(unsigned long long& a, unsigned long long x,
                                     unsigned long long y) {
    asm("fma.rn.f32x2 %0, %1, %2, %0;" : "+l"(a) : "l"(x), "l"(y));
}
__device__ __forceinline__ float2 unpack2(unsigned long long v) {
    float lo, hi; asm("mov.b64 {%0, %1}, %2;" : "=f"(lo), "=f"(hi) : "l"(v));
    return make_float2(lo, hi);
}
__device__ __forceinline__ int i4(const int4 v, int z) {
    return z == 0 ? v.x : z == 1 ? v.y : z == 2 ? v.z : v.w;
}
__device__ __forceinline__ unsigned t32(float f) {
    unsigned r; asm("cvt.rna.tf32.f32 %0, %1;" : "=r"(r) : "f"(f)); return r;
}
__device__ __forceinline__ float t32f(float f) {
    return __uint_as_float(t32(f));
}
__device__ __forceinline__ void mma8(float* c, const unsigned* a, const unsigned* b) {
    asm("mma.sync.aligned.m16n8k8.row.col.f32.tf32.tf32.f32 "
        "{%0,%1,%2,%3},{%4,%5,%6,%7},{%8,%9},{%0,%1,%2,%3};"
        : "+f"(c[0]), "+f"(c[1]), "+f"(c[2]), "+f"(c[3])
        : "r"(a[0]), "r"(a[1]), "r"(a[2]), "r"(a[3]), "r"(b[0]), "r"(b[1]));
}

// ---------------- GP ----------------
struct GP {
    const float *A, *B, *bias, *meanp, *ivsp; float* C;
    int M, N, K, lda, ldb, subM, bmode, sh;
    int CI, IH, IW, OW, OHW, s, pp, pd;
    int4 Mz, Kz, wOffz, HWpz, OWpz, pyz, pxz, ky0z, kx0z, nkxz;
    int OHfull, OWfull, CO, act;
};

// ---------------- tf32 MMA implicit GEMM (swizzled fragment-major A smem) -------
template<int BN, int AM, int EP>
__global__ void __launch_bounds__(256, 2) gemm_m(GP p)
{
    constexpr int BK = 16;
    constexpr int NWN = BN / 32;
    constexpr int NWM = 8 / NWN;
    constexpr int RW = 128 / NWM;
    constexpr int MT = RW / 16;
    constexpr int NVB = BN / 64;
    __shared__ __align__(16) float As[2][2][8][128];
    __shared__ __align__(16) float Bs[2][BK][BN + 8];
    const int tid = threadIdx.x;
    const int z = blockIdx.z;
    const int M = (AM == 2) ? i4(p.Mz, z) : p.M;
    const int K = (AM == 2) ? i4(p.Kz, z) : p.K;
    const int m0 = blockIdx.y * 128;
    if (m0 >= M) return;
    const int n0 = blockIdx.x * BN;
    const int koff = (EP == 1) ? z * K : 0;
    const int lane = tid & 31, wid = tid >> 5;
    const int warp_m = wid / NWN, warp_n = wid % NWN;
    const int g = lane >> 2, tig = lane & 3;

    int HWp = 0, OWp = 0, py = 0, px = 0, ky0 = 0, kx0 = 0, nkx = 1;
    if (AM == 2) {
        HWp = i4(p.HWpz, z); OWp = i4(p.OWpz, z); py = i4(p.pyz, z); px = i4(p.pxz, z);
        ky0 = i4(p.ky0z, z); kx0 = i4(p.kx0z, z); nkx = i4(p.nkxz, z);
    }
    const float* Bb = p.B + ((AM == 2) ? (size_t)i4(p.wOffz, z) : 0);

    const int lanoff = (tid & 3) << 2;
    const float* meanp_t = p.meanp + lanoff;
    const float* aptr[2];
    int amask[2];
    int ry = 0, rx = 0;
    if (AM == 2) { ry = (py + p.pd) & 1; rx = (px + p.pd) & 1; }
#pragma unroll
    for (int i = 0; i < 2; i++) {
        int r = (tid >> 2) + 64 * i;
        int gm = m0 + r;
        bool ok = gm < M;
        int gg = ok ? gm : 0;
        int msk = 0;
        if (AM == 1) {
            int b = gg / p.OHW, hw = gg - b * p.OHW;
            int oy = hw / p.OW, ox = hw - oy * p.OW;
            int ay = oy * p.s - p.pp, ax = ox * p.s - p.pp;
            if (ok) {
#pragma unroll
                for (int tap = 0; tap < 9; tap++) {
                    int ky = tap / 3, kx = tap - 3 * (tap / 3);
                    if ((unsigned)(ay + ky) < (unsigned)p.IH &&
                        (unsigned)(ax + kx) < (unsigned)p.IW) msk |= 1 << tap;
                }
            }
            aptr[i] = p.A + (long)b * p.IH * p.IW * p.CI +
                      (long)(ay * p.IW + ax) * p.CI + lanoff;
        } else {
            int b = gg / HWp, rr2 = gg - b * HWp;
            int ly = rr2 / OWp, lx = rr2 - ly * OWp;
            int aoy = py + 2 * ly - p.pd, aox = px + 2 * lx - p.pd;
            int nky = 2 - ky0;
            int ntc = nky * nkx;
            if (ok) {
                for (int tt = 0; tt < ntc; tt++) {
                    int jy = (nkx == 2) ? (tt >> 1) : tt;
                    int jx = (nkx == 2) ? (tt & 1) : 0;
                    int ky = ky0 + 2 * jy, kx = kx0 + 2 * jx;
                    int tyy = aoy + ky, txx = aox + kx;
                    if (tyy >= 0 && txx >= 0 && (tyy >> 1) < p.IH && (txx >> 1) < p.IW)
                        msk |= 1 << tt;
                }
            }
            int ey = (aoy - ry) >> 1, ex = (aox - rx) >> 1;
            aptr[i] = p.A + (long)b * p.IH * p.IW * p.CI +
                      (long)(ey * p.IW + ex) * p.CI + lanoff;
        }
        amask[i] = msk;
    }

    const int NT = K / BK;
    float4 ra[2], rb[NVB];

    auto loadA = [&](int t) {
        const int k0 = koff + t * BK;
        const int kr = k0 & (p.CI - 1);
        if (AM == 1) {
            int tap = k0 >> p.sh;
            int ky = tap / 3, kx = tap - 3 * ky;
            int dt = (ky * p.IW + kx) * p.CI + kr;
            const float4 mu = *(const float4*)(meanp_t + kr);
#pragma unroll
            for (int i = 0; i < 2; i++) {
                float4 tmp = make_float4(0.f, 0.f, 0.f, 0.f);
                if ((amask[i] >> tap) & 1) {
                    tmp = *(const float4*)(aptr[i] + dt);
                    tmp.x -= mu.x; tmp.y -= mu.y; tmp.z -= mu.z; tmp.w -= mu.w;
                }
                ra[i] = tmp;
            }
        } else {
            int tt = k0 >> p.sh;
            int jy, jx;
            if (nkx == 2) { jy = tt >> 1; jx = tt & 1; } else { jy = tt; jx = 0; }
            int dt = ((ry + jy) * p.IW + (rx + jx)) * p.CI + kr;
#pragma unroll
            for (int i = 0; i < 2; i++) {
                float4 tmp = make_float4(0.f, 0.f, 0.f, 0.f);
                if ((amask[i] >> tt) & 1)
                    tmp = *(const float4*)(aptr[i] + dt);
                ra[i] = tmp;
            }
        }
    };
    auto loadB = [&](int t) {
        const int k0 = koff + t * BK;
#pragma unroll
        for (int i = 0; i < NVB; i++) {
            int vid = tid + i * 256;
            int n4 = vid % (BN / 4), kc = vid / (BN / 4);
            rb[i] = *(const float4*)(Bb + (size_t)(k0 + kc) * p.ldb + n0 + n4 * 4);
        }
    };
    auto storeT = [&](int buf) {
#pragma unroll
        for (int i = 0; i < 2; i++) {
            int vid = tid + i * 256;
            int r = vid >> 2, kc = (vid & 3) << 2;
            int c = kc >> 3, h = (kc >> 2) & 1;
            int gi = r & 7;
            int s2 = (gi >> 1) & 3;
            float* tb = &As[buf][c][r >> 4][gi * 16 + ((r >> 3) & 1) + (h << 1)];
            tb[(0 ^ s2) * 4] = t32f(ra[i].x);
            tb[(1 ^ s2) * 4] = t32f(ra[i].y);
            tb[(2 ^ s2) * 4] = t32f(ra[i].z);
            tb[(3 ^ s2) * 4] = t32f(ra[i].w);
        }
#pragma unroll
        for (int i = 0; i < NVB; i++) {
            int vid = tid + i * 256;
            int n4 = vid % (BN / 4), kc = vid / (BN / 4);
            float4 cv = make_float4(t32f(rb[i].x), t32f(rb[i].y),
                                    t32f(rb[i].z), t32f(rb[i].w));
            *(float4*)&Bs[buf][kc][n4 * 4] = cv;
        }
    };

    float acc[MT][4][4];
#pragma unroll
    for (int mt = 0; mt < MT; mt++)
#pragma unroll
        for (int nt = 0; nt < 4; nt++)
#pragma unroll
            for (int r = 0; r < 4; r++) acc[mt][nt][r] = 0.f;

    loadA(0); loadB(0);
    storeT(0);
    __syncthreads();

    const int aoffs = g * 16 + ((tig ^ ((g >> 1) & 3)) << 2);

    for (int t = 0; t < NT; t++) {
        int cur = t & 1;
        if (t + 1 < NT) { loadA(t + 1); loadB(t + 1); }
#pragma unroll
        for (int c8 = 0; c8 < 2; c8++) {
            unsigned aF[MT][4], bF[4][2];
#pragma unroll
            for (int mt = 0; mt < MT; mt++) {
                const float4 av = *(const float4*)&As[cur][c8][warp_m * MT + mt][aoffs];
                aF[mt][0] = __float_as_uint(av.x);
                aF[mt][1] = __float_as_uint(av.y);
                aF[mt][2] = __float_as_uint(av.z);
                aF[mt][3] = __float_as_uint(av.w);
            }
#pragma unroll
            for (int nt = 0; nt < 4; nt++) {
                int nc = warp_n * 32 + nt * 8 + g;
                bF[nt][0] = __float_as_uint(Bs[cur][c8 * 8 + tig][nc]);
                bF[nt][1] = __float_as_uint(Bs[cur][c8 * 8 + tig + 4][nc]);
            }
#pragma unroll
            for (int mt = 0; mt < MT; mt++)
#pragma unroll
                for (int nt = 0; nt < 4; nt++)
                    mma8(acc[mt][nt], aF[mt], bF[nt]);
        }
        if (t + 1 < NT) storeT((t + 1) & 1);
        __syncthreads();
    }

#pragma unroll
    for (int mt = 0; mt < MT; mt++) {
#pragma unroll
        for (int half = 0; half < 2; half++) {
            int r = m0 + warp_m * RW + mt * 16 + g + 8 * half;
            if (r >= M) continue;
            if (EP == 1) {
                float* Cp = p.C + ((size_t)z * p.M + r) * p.N;
#pragma unroll
                for (int nt = 0; nt < 4; nt++) {
                    int c0 = n0 + warp_n * 32 + nt * 8 + 2 * tig;
                    *(float2*)(Cp + c0) = half
                        ? make_float2(acc[mt][nt][2], acc[mt][nt][3])
                        : make_float2(acc[mt][nt][0], acc[mt][nt][1]);
                }
            } else {
                int b = r / HWp, rr = r - b * HWp;
                int ly = rr / OWp, lx = rr - ly * OWp;
                int oy = py + 2 * ly, ox = px + 2 * lx;
                size_t base = (((size_t)b * p.OHfull + oy) * p.OWfull + ox) * (size_t)p.CO;
#pragma unroll
                for (int nt = 0; nt < 4; nt++) {
                    int c0 = n0 + warp_n * 32 + nt * 8 + 2 * tig;
                    float2 bb = *(const float2*)(p.bias + c0);
                    float2 v = half
                        ? make_float2(acc[mt][nt][2], acc[mt][nt][3])
                        : make_float2(acc[mt][nt][0], acc[mt][nt][1]);
                    v.x += bb.x; v.y += bb.y;
                    *(float2*)(p.C + base + c0) = v;
                }
            }
        }
    }
}

// ---------------- fp32 GEMM (fc / dec only) ----------------
template<int BM, int BN, int TM, int TN, int EP>
__global__ void __launch_bounds__(256, 2) gemm_u(GP p)
{
    constexpr int BK = 16;
    constexpr int NVA = (BM * BK) / 1024;
    constexpr int NVB = (BN * BK) / 1024;
    constexpr int TP = TM / 2;
    __shared__ __align__(16) float As[2][BK][BM + 4];
    __shared__ __align__(16) float Bs[2][BK][BN + 4];
    const int tid = threadIdx.x, tx = tid & 15, ty = tid >> 4;
    const int z = blockIdx.z;
    const int M = p.M, K = p.K;
    const int m0 = blockIdx.y * BM;
    if (m0 >= M) return;
    const int n0 = blockIdx.x * BN;
    const int koff = (EP == 1) ? z * K : 0;
    const int NT = K / BK;
    float4 ra[NVA], rb[NVB];
    const bool vecB = ((p.ldb & 3) == 0) && (n0 + BN <= p.N);

    auto loadA = [&](int t) {
        const int k0 = koff + t * BK;
#pragma unroll
        for (int i = 0; i < NVA; i++) {
            int vid = tid + i * 256;
            int r = vid >> 2, kc = (vid & 3) << 2;
            int gm = m0 + r;
            float4 v = make_float4(0.f, 0.f, 0.f, 0.f);
            if (gm < M) {
                v = *(const float4*)(p.A + (size_t)gm * p.lda + k0 + kc);
                if (p.subM) {
                    const float4 mu = *(const float4*)(p.meanp + ((k0 + kc) & 1023));
                    v.x -= mu.x; v.y -= mu.y; v.z -= mu.z; v.w -= mu.w;
                }
            }
            ra[i] = v;
        }
    };
    auto loadB = [&](int t) {
        const int k0 = koff + t * BK;
#pragma unroll
        for (int i = 0; i < NVB; i++) {
            int vid = tid + i * 256;
            int n4 = vid % (BN / 4), kc = vid / (BN / 4);
            int gk = k0 + kc;
            int row = (p.bmode == 2) ? (((gk & 1023) << 4) + (gk >> 10)) : gk;
            float4 v;
            if (vecB) {
                v = *(const float4*)(p.B + (size_t)row * p.ldb + n0 + n4 * 4);
            } else {
                float w[4];
#pragma unroll
                for (int j = 0; j < 4; j++) {
                    int gn = n0 + n4 * 4 + j;
                    w[j] = (gn < p.N) ? p.B[(size_t)row * p.ldb + gn] : 0.f;
                }
                v = make_float4(w[0], w[1], w[2], w[3]);
            }
            if (p.bmode == 2) {
                float s = p.ivsp[gk & 1023];
                v.x *= s; v.y *= s; v.z *= s; v.w *= s;
            }
            rb[i] = v;
        }
    };
    auto storeT = [&](int buf) {
#pragma unroll
        for (int i = 0; i < NVA; i++) {
            int vid = tid + i * 256;
            int r = vid >> 2, kc = (vid & 3) << 2;
            As[buf][kc + 0][r] = ra[i].x;
            As[buf][kc + 1][r] = ra[i].y;
            As[buf][kc + 2][r] = ra[i].z;
            As[buf][kc + 3][r] = ra[i].w;
        }
#pragma unroll
        for (int i = 0; i < NVB; i++) {
            int vid = tid + i * 256;
            int n4 = vid % (BN / 4), kc = vid / (BN / 4);
            *(float4*)&Bs[buf][kc][n4 * 4] = rb[i];
        }
    };

    unsigned long long acc2[TP][TN];
#pragma unroll
    for (int q = 0; q < TP; q++)
#pragma unroll
        for (int j = 0; j < TN; j++) acc2[q][j] = 0ull;

    loadA(0); loadB(0);
    storeT(0);
    __syncthreads();

    for (int t = 0; t < NT; t++) {
        int cur = t & 1;
        if (t + 1 < NT) { loadA(t + 1); loadB(t + 1); }
#pragma unroll
        for (int k = 0; k < BK; k++) {
            unsigned long long ap[TP];
#pragma unroll
            for (int g = 0; g < TM / 4; g++) {
                const ulonglong2 av = *(const ulonglong2*)&As[cur][k][g * 64 + tx * 4];
                ap[2 * g] = av.x; ap[2 * g + 1] = av.y;
            }
            unsigned long long bb[TN];
#pragma unroll
            for (int h = 0; h < TN / 4; h++) {
                const float4 b4 = *(const float4*)&Bs[cur][k][h * 64 + ty * 4];
                bb[4 * h + 0] = pack2(b4.x); bb[4 * h + 1] = pack2(b4.y);
                bb[4 * h + 2] = pack2(b4.z); bb[4 * h + 3] = pack2(b4.w);
            }
#pragma unroll
            for (int q = 0; q < TP; q++)
#pragma unroll
                for (int j = 0; j < TN; j++)
                    fma2(acc2[q][j], ap[q], bb[j]);
        }
        if (t + 1 < NT) storeT((t + 1) & 1);
        __syncthreads();
    }

#pragma unroll
    for (int q = 0; q < TP; q++) {
        float2 vv[TN];
#pragma unroll
        for (int j = 0; j < TN; j++) vv[j] = unpack2(acc2[q][j]);
#pragma unroll
        for (int e = 0; e < 2; e++) {
            int gm = m0 + (q >> 1) * 64 + (tx << 2) + ((q & 1) << 1) + e;
            if (gm >= M) continue;
            if (EP == 1) {
                float* Cp = p.C + ((size_t)z * p.M + gm) * p.N;
#pragma unroll
                for (int j = 0; j < TN; j++) {
                    int gn = n0 + (j >> 2) * 64 + (ty << 2) + (j & 3);
                    if (gn < p.N) Cp[gn] = e ? vv[j].y : vv[j].x;
                }
            } else {
                size_t base = (size_t)gm * p.N;
#pragma unroll
                for (int j = 0; j < TN; j++) {
                    int gn = n0 + (j >> 2) * 64 + (ty << 2) + (j & 3);
                    if (gn < p.N) p.C[base + gn] = (e ? vv[j].y : vv[j].x) + p.bias[gn];
                }
            }
        }
    }
}

// ---------------- aux kernels ----------------

__global__ void conv1_nhwc(const float* __restrict__ x, const float* __restrict__ w,
                           const float* __restrict__ b, float* __restrict__ h1) {
    if (blockIdx.x == 0 && blockIdx.y == 0) {
        for (int i = threadIdx.x; i < 4096; i += 128) { g_bnsum[i] = 0.f; g_bnss[i] = 0.f; }
    }
    int pix = blockIdx.x, img = blockIdx.y, co = threadIdx.x;
    int oy = pix >> 5, ox = pix & 31;
    __shared__ float xv[9];
    if (co < 9) {
        int ky = co / 3, kx = co % 3;
        int iy = 2 * oy - 1 + ky, ix = 2 * ox - 1 + kx;
        xv[co] = ((unsigned)iy < 64u && (unsigned)ix < 64u)
                     ? x[(size_t)img * 4096 + iy * 64 + ix] : 0.f;
    }
    __syncthreads();
    float acc = b[co];
#pragma unroll
    for (int t = 0; t < 9; t++) acc = fmaf(xv[t], w[co * 9 + t], acc);
    acc = (acc >= 0.f) ? acc : 0.01f * acc;
    h1[((size_t)img * 1024 + pix) * 128 + co] = acc;
}

__global__ void bn_part(const float* __restrict__ h, int C, long total, int L) {
    long stride = (long)gridDim.x * 256;
    long e = (long)blockIdx.x * 256 + threadIdx.x;
    if (e >= total) return;
    int c = (int)(e % C);
    float s = 0.f, ss = 0.f;
    for (; e < total; e += stride) { float v = h[e]; s += v; ss += v * v; }
    atomicAdd(&g_bnsum[L * 1024 + c], s);
    atomicAdd(&g_bnss[L * 1024 + c], ss);
}

// fused split-K reduce + bias + leaky + bn stats accumulation (region L)
// grid-stride, 1024 blocks x 256: stride*4 floats = 2^20, divisible by C
__global__ void reduce_bn(const float4* __restrict__ part, const float4* __restrict__ bias,
                          float4* __restrict__ out, int total4, int n4, int S, int L) {
    long stride = (long)gridDim.x * 256;
    long e0 = (long)blockIdx.x * 256 + threadIdx.x;
    int c = (int)((e0 * 4) % ((long)n4 * 4));
    float4 sm = make_float4(0.f, 0.f, 0.f, 0.f);
    float4 sq = make_float4(0.f, 0.f, 0.f, 0.f);
    for (long i = e0; i < total4; i += stride) {
        float4 s = part[i];
        for (int z = 1; z < S; z++) {
            float4 q = part[(size_t)z * total4 + i];
            s.x += q.x; s.y += q.y; s.z += q.z; s.w += q.w;
        }
        float4 b = bias[i % n4];
        s.x += b.x; s.y += b.y; s.z += b.z; s.w += b.w;
        s.x = (s.x >= 0.f) ? s.x : 0.01f * s.x;
        s.y = (s.y >= 0.f) ? s.y : 0.01f * s.y;
        s.z = (s.z >= 0.f) ? s.z : 0.01f * s.z;
        s.w = (s.w >= 0.f) ? s.w : 0.01f * s.w;
        out[i] = s;
        sm.x += s.x; sm.y += s.y; sm.z += s.z; sm.w += s.w;
        sq.x += s.x * s.x; sq.y += s.y * s.y; sq.z += s.z * s.z; sq.w += s.w * s.w;
    }
    float* bs = &g_bnsum[L * 1024 + c];
    float* bq = &g_bnss[L * 1024 + c];
    atomicAdd(bs + 0, sm.x); atomicAdd(bs + 1, sm.y);
    atomicAdd(bs + 2, sm.z); atomicAdd(bs + 3, sm.w);
    atomicAdd(bq + 0, sq.x); atomicAdd(bq + 1, sq.y);
    atomicAdd(bq + 2, sq.z); atomicAdd(bq + 3, sq.w);
}

__global__ void wt_fold(const float* __restrict__ w, float* __restrict__ wt,
                        int CI, int CO, int L, float cnt) {
    int c0 = blockIdx.x * 32, o0 = blockIdx.y * 32;
    __shared__ float tile[32][289];
    __shared__ float sig[32];
    int t = threadIdx.x;
    if (t < 32) {
        int ci = c0 + t;
        float m = g_bnsum[L * 1024 + ci] / cnt;
        float var = g_bnss[L * 1024 + ci] / cnt - m * m;
        float s = rsqrtf(var + 1e-5f);
        sig[t] = s;
        if (o0 == 0) { g_mean[L * 1024 + ci] = m; g_invstd[L * 1024 + ci] = s; }
    }
    __syncthreads();
    for (int i = t; i < 32 * 288; i += 256) {
        int r = i / 288, j = i - r * 288;
        tile[r][j] = w[((size_t)(o0 + r) * CI + c0) * 9 + j];
    }
    __syncthreads();
    for (int i = t; i < 288 * 32; i += 256) {
        int tt = i & 31, q = i >> 5;
        int cc = q / 9, tap = q - cc * 9;
        int k = tap * CI + c0 + cc;
        wt[(size_t)k * CO + o0 + tt] = tile[tt][cc * 9 + tap] * sig[cc];
    }
}

__global__ void bn_fin3(float cnt) {
    int c = blockIdx.x * 256 + threadIdx.x;
    if (c < 1024) {
        float m = g_bnsum[3072 + c] / cnt;
        float var = g_bnss[3072 + c] / cnt - m * m;
        g_mean[3072 + c] = m;
        g_invstd[3072 + c] = rsqrtf(var + 1e-5f);
    }
}

__global__ void wt_par(const float* __restrict__ w, float* __restrict__ wt,
                       int CI, int CO, int4 Ktz, int4 wOffz, int4 ky0z, int4 kx0z, int4 nkxz) {
    int z = blockIdx.z;
    int Kt = i4(Ktz, z);
    int idx = blockIdx.x * 256 + threadIdx.x;
    if (idx >= Kt * CO) return;
    int k = idx / CO, co = idx - k * CO;
    int ci = k % CI, tt = k / CI;
    int nkx = i4(nkxz, z);
    int jy, jx;
    if (nkx == 2) { jy = tt >> 1; jx = tt & 1; } else { jy = tt; jx = 0; }
    int ky = i4(ky0z, z) + 2 * jy, kx = i4(kx0z, z) + 2 * jx;
    wt[i4(wOffz, z) + idx] = w[(((size_t)ci * CO + co) * 3 + (2 - ky)) * 3 + (2 - kx)];
}

__global__ void perm_dec(const float* __restrict__ w, const float* __restrict__ b,
                         float* __restrict__ ow, float* __restrict__ ob) {
    long idx = (long)blockIdx.x * 256 + threadIdx.x;
    if (idx >= (long)800 * 9216) return;
    int k = (int)(idx / 9216), n = (int)(idx - (long)k * 9216);
    int hw = n >> 10, c = n & 1023;
    ow[idx] = w[(size_t)k * 9216 + c * 9 + hw];
    if (k == 0) ob[n] = b[c * 9 + hw];
}

__global__ void reduce_fc(const float* __restrict__ part, const float* __restrict__ bias,
                          float* __restrict__ out) {
    int idx = blockIdx.x * 256 + threadIdx.x;
    if (idx >= 80000) return;
    int n = idx % 800;
    float s = 0.f;
#pragma unroll
    for (int z = 0; z < 8; z++) s += part[(size_t)z * 80000 + idx];
    s += bias[n];
    out[idx] = fmaxf(s, 0.f);
}

__global__ void init_tab(float* tab) {
    int k = blockIdx.x * 256 + threadIdx.x;
    if (k < 800) tab[k] = (float)cos(2.0 * 3.141592653589793238462643 * (double)k / 800.0);
}
__global__ void compute_R(const float* __restrict__ eig, const float* __restrict__ tab,
                          float* __restrict__ R) {
    int b = blockIdx.x;
    __shared__ float s[800], t[800];
    for (int i = threadIdx.x; i < 800; i += 256) { s[i] = eig[b * 800 + i]; t[i] = tab[i]; }
    __syncthreads();
    for (int o = threadIdx.x; o < 800; o += 256) {
        int m = o >> 3, l = o & 7;
        float acc = 0.f;
        for (int q = 0; q < 800; q++) {
            int mp = q >> 3, lp = q & 7;
            int ph = (8 * m * mp + 100 * l * lp) % 800;
            acc += s[q] * t[ph];
        }
        R[b * 800 + o] = acc;
    }
}

// 16 rows per block: grid (50, 100)
__global__ void write_C16(const float* __restrict__ R, float* __restrict__ C) {
    int b = blockIdx.y, i0 = blockIdx.x * 16;
    __shared__ float r[800];
    const float inv = 0.035355339059327376f;
    for (int q = threadIdx.x; q < 800; q += 256) r[q] = R[b * 800 + q] * inv;
    __syncthreads();
    for (int i = i0; i < i0 + 16; i++) {
        size_t base = ((size_t)b * 800 + i) * 800;
        for (int j = threadIdx.x; j < 800; j += 256)
            C[base + j] = r[(i - j + 800) % 800];
    }
}

__global__ void ct5_nhwc(const float* __restrict__ t4, const float* __restrict__ w,
                         const float* __restrict__ bias, float* __restrict__ out) {
    __shared__ float ws[576];
    for (int i = threadIdx.x; i < 576; i += 128) {
        int tap = i >> 6, ci = i & 63;
        int ky = tap / 3, kx = tap % 3;
        ws[i] = w[ci * 9 + (2 - ky) * 3 + (2 - kx)];
    }
    __syncthreads();
    int b = blockIdx.y;
    int o = blockIdx.x * 128 + threadIdx.x;
    if (o >= 2401) return;
    int oy = o / 49, ox = o % 49;
    float acc = bias[0];
#pragma unroll
    for (int ky = 0; ky < 3; ky++) {
        int iy = oy + ky - 2;
        if ((unsigned)iy >= 47u) continue;
#pragma unroll
        for (int kx = 0; kx < 3; kx++) {
            int ix = ox + kx - 2;
            if ((unsigned)ix >= 47u) continue;
            const float4* p4 = (const float4*)(t4 + ((size_t)(b * 47 + iy) * 47 + ix) * 64);
            const float4* w4 = (const float4*)(ws + (ky * 3 + kx) * 64);
#pragma unroll
            for (int q = 0; q < 16; q++) {
                float4 v = p4[q], wv = w4[q];
                acc += v.x * wv.x + v.y * wv.y + v.z * wv.z + v.w * wv.w;
            }
        }
    }
    out[(size_t)b * 2401 + o] = acc;
}

// ---------------- host ----------------
static float* symaddr(const void* s) {
    void* p = nullptr; cudaGetSymbolAddress(&p, s); return (float*)p;
}
static int log2i(int v) { int s = 0; while ((1 << s) < v) s++; return s; }

struct PM { int4 Mz, Kz, wOff, HWpz, OWpz, pyz, pxz, ky0z, kx0z, nkxz; int maxM, maxKt; };
static PM pmeta(int B, int CI, int OH, int pd, int CO) {
    PM m{}; int Mv[4], Kv[4], wo[4], hwp[4], owp[4], pyv[4], pxv[4], k0v[4], kx0v[4], nkxv[4];
    int wacc = 0, i = 0; m.maxM = 0; m.maxKt = 0;
    for (int py = 0; py < 2; py++)
        for (int px = 0; px < 2; px++, i++) {
            int ky0 = ((pd - py) % 2 + 2) % 2, nky = 2 - ky0;
            int kx0 = ((pd - px) % 2 + 2) % 2, nkx = 2 - kx0;
            int OHp = (OH - py + 1) / 2, OWp = (OH - px + 1) / 2;
            int Kt = CI * nky * nkx, Mp = B * OHp * OWp;
            Mv[i] = Mp; Kv[i] = Kt; wo[i] = wacc;
            hwp[i] = OHp * OWp; owp[i] = OWp;
            pyv[i] = py; pxv[i] = px; k0v[i] = ky0; kx0v[i] = kx0; nkxv[i] = nkx;
            wacc += CO * Kt;
            if (Mp > m.maxM) m.maxM = Mp;
            if (Kt > m.maxKt) m.maxKt = Kt;
        }
    m.Mz = make_int4(Mv[0], Mv[1], Mv[2], Mv[3]);
    m.Kz = make_int4(Kv[0], Kv[1], Kv[2], Kv[3]);
    m.wOff = make_int4(wo[0], wo[1], wo[2], wo[3]);
    m.HWpz = make_int4(hwp[0], hwp[1], hwp[2], hwp[3]);
    m.OWpz = make_int4(owp[0], owp[1], owp[2], owp[3]);
    m.pyz = make_int4(pyv[0], pyv[1], pyv[2], pyv[3]);
    m.pxz = make_int4(pxv[0], pxv[1], pxv[2], pxv[3]);
    m.ky0z = make_int4(k0v[0], k0v[1], k0v[2], k0v[3]);
    m.kx0z = make_int4(kx0v[0], kx0v[1], kx0v[2], kx0v[3]);
    m.nkxz = make_int4(nkxv[0], nkxv[1], nkxv[2], nkxv[3]);
    return m;
}

static void conv_fwd_gemm(const float* in, const float* bias, float* outp,
                          int B, int CI, int CO, int IH, int OWo, int L, int splitK,
                          int bnL) {
    GP p{};
    p.A = in; p.B = symaddr(g_wT); p.bias = bias;
    p.meanp = symaddr(g_mean) + L * 1024;
    p.N = CO; p.ldb = CO; p.sh = log2i(CI);
    p.CI = CI; p.IH = IH; p.IW = IH; p.OW = OWo; p.OHW = OWo * OWo; p.s = 2; p.pp = 1;
    p.M = B * p.OHW;
    p.C = symaddr(g_part); p.K = 9 * CI / splitK;
    dim3 g(CO / 128, (p.M + 127) / 128, splitK);
    gemm_m<128, 1, 1><<<g, 256>>>(p);
    int total4 = p.M * CO / 4;
    int nb = (total4 + 255) / 256;
    if (nb > 1024) nb = 1024;
    reduce_bn<<<nb, 256>>>(
        (const float4*)symaddr(g_part), (const float4*)bias, (float4*)outp,
        total4, CO / 4, splitK, bnL);
}

static void convT_mma(const float* in, const float* wraw, const float* bias,
                      float* out, int B, int CI, int CO, int IH, int OH, int pd) {
    float* wT = symaddr(g_wT);
    PM m = pmeta(B, CI, OH, pd, CO);
    wt_par<<<dim3((m.maxKt * CO + 255) / 256, 1, 4), 256>>>(
        wraw, wT, CI, CO, m.Kz, m.wOff, m.ky0z, m.kx0z, m.nkxz);
    GP p{};
    p.A = in; p.B = wT; p.bias = bias; p.C = out;
    p.N = CO; p.ldb = CO; p.CI = CI; p.IH = IH; p.IW = IH; p.pd = pd;
    p.sh = log2i(CI);
    p.Mz = m.Mz; p.Kz = m.Kz; p.wOffz = m.wOff; p.HWpz = m.HWpz; p.OWpz = m.OWpz;
    p.pyz = m.pyz; p.pxz = m.pxz; p.ky0z = m.ky0z; p.kx0z = m.kx0z; p.nkxz = m.nkxz;
    p.OHfull = OH; p.OWfull = OH; p.CO = CO;
    if (CO >= 128) {
        dim3 g(CO / 128, (m.maxM + 127) / 128, 4);
        gemm_m<128, 2, 3><<<g, 256>>>(p);
    } else {
        dim3 g(CO / 64, (m.maxM + 127) / 128, 4);
        gemm_m<64, 2, 3><<<g, 256>>>(p);
    }
}

extern "C" void kernel_launch(void* const* d_in, const int* in_sizes, int n_in,
                              void* d_out, int out_size) {
    const float* x       = (const float*)d_in[0];
    const float* conv1_w = (const float*)d_in[1];
    const float* conv1_b = (const float*)d_in[2];
    const float* conv2_w = (const float*)d_in[3];
    const float* conv2_b = (const float*)d_in[4];
    const float* conv3_w = (const float*)d_in[5];
    const float* conv3_b = (const float*)d_in[6];
    const float* conv4_w = (const float*)d_in[7];
    const float* conv4_b = (const float*)d_in[8];
    const float* fc_w    = (const float*)d_in[9];
    const float* fc_b    = (const float*)d_in[10];
    const float* dec_w   = (const float*)d_in[11];
    const float* dec_b   = (const float*)d_in[12];
    const float* ct1_w   = (const float*)d_in[13];
    const float* ct1_b   = (const float*)d_in[14];
    const float* ct2_w   = (const float*)d_in[15];
    const float* ct2_b   = (const float*)d_in[16];
    const float* ct3_w   = (const float*)d_in[17];
    const float* ct3_b   = (const float*)d_in[18];
    const float* ct4_w   = (const float*)d_in[19];
    const float* ct4_b   = (const float*)d_in[20];
    const float* ct5_w   = (const float*)d_in[21];
    const float* ct5_b   = (const float*)d_in[22];

    float* out = (float*)d_out;
    float* out_d   = out;
    float* out_C   = out + 240100;
    float* out_eig = out + 240100 + 64000000;

    float* h1 = symaddr(g_h1);
    float* h2 = symaddr(g_h2);
    float* h3 = symaddr(g_h3);
    float* h4 = symaddr(g_h4);
    float* part = symaddr(g_part);
    float* wT = symaddr(g_wT);
    float* R  = symaddr(g_R);
    float* tab = symaddr(g_tab);
    float* d0 = symaddr(g_d0);
    float* t1 = symaddr(g_t1);
    float* t2 = symaddr(g_t2);
    float* t3 = symaddr(g_t3);
    float* t4 = symaddr(g_t4);
    float* biasP = symaddr(g_bias);
    const int B = 100;

    // encoder (NHWC, BN folded, tf32 mma + split-K; reduce fuses bias/leaky/bn)
    conv1_nhwc<<<dim3(1024, B), 128>>>(x, conv1_w, conv1_b, h1);                 // 1
    bn_part<<<1024, 256>>>(h1, 128, (long)13107200, 0);                          // 2
    wt_fold<<<dim3(4, 8), 256>>>(conv2_w, wT, 128, 256, 0, 102400.f);            // 3
    conv_fwd_gemm(h1, conv2_b, h2, B, 128, 256, 32, 16, 0, 3, 1);                // 4 profiled
    wt_fold<<<dim3(8, 32), 256>>>(conv3_w, wT, 256, 1024, 1, 25600.f);
    conv_fwd_gemm(h2, conv3_b, h3, B, 256, 1024, 16, 8, 1, 3, 2);
    wt_fold<<<dim3(32, 32), 256>>>(conv4_w, wT, 1024, 1024, 2, 6400.f);
    conv_fwd_gemm(h3, conv4_b, h4, B, 1024, 1024, 8, 4, 2, 12, 3);
    bn_fin3<<<4, 256>>>(1600.f);

    // fc: fp32, B = fc_w in-place row remap + invstd fold; mean subtract in A
    {
        GP p{};
        p.A = h4; p.B = fc_w; p.bias = fc_b; p.C = part;
        p.meanp = symaddr(g_mean) + 3072; p.subM = 1;
        p.ivsp = symaddr(g_invstd) + 3072; p.bmode = 2;
        p.M = 100; p.N = 800; p.K = 2048; p.lda = 16384; p.ldb = 800;
        dim3 g(13, 2, 8);
        gemm_u<64, 64, 4, 4, 1><<<g, 256>>>(p);
    }
    reduce_fc<<<(80000 + 255) / 256, 256>>>(part, fc_b, out_eig);

    // spectral
    init_tab<<<4, 256>>>(tab);
    compute_R<<<B, 256>>>(out_eig, tab, R);
    write_C16<<<dim3(50, B), 256>>>(R, out_C);

    // dec -> d0 NHWC (fp32)
    perm_dec<<<(int)(((long)800 * 9216 + 255) / 256), 256>>>(dec_w, dec_b, wT, biasP);
    {
        GP p{};
        p.A = R; p.B = wT; p.bias = biasP; p.C = d0;
        p.M = 100; p.N = 9216; p.K = 800; p.lda = 800; p.ldb = 9216;
        dim3 g(144, 2, 1);
        gemm_u<64, 64, 4, 4, 0><<<g, 256>>>(p);
    }

    // decoder convT (tf32 mma)
    convT_mma(d0, ct1_w, ct1_b, t1, B, 1024, 512, 3, 5, 1);
    convT_mma(t1, ct2_w, ct2_b, t2, B, 512, 256, 5, 11, 2);
    convT_mma(t2, ct3_w, ct3_b, t3, B, 256, 128, 11, 23, 2);
    convT_mma(t3, ct4_w, ct4_b, t4, B, 128, 64, 23, 47, 2);
    ct5_nhwc<<<dim3((2401 + 127) / 128, B), 128>>>(t4, ct5_w, ct5_b, out_d);
}

// round 17
// speedup vs baseline: 1.0894x; 1.0894x over previous
#include <cuda_runtime.h>

// ---------------- scratch ----------------
__device__ __align__(16) float g_wT[13200000];
__device__ __align__(16) float g_bias[9216];
__device__ __align__(16) float g_h1[13107200];   // 100x32x32x128 NHWC
__device__ __align__(16) float g_h2[6553600];    // 100x16x16x256
__device__ __align__(16) float g_h3[6553600];    // 100x8x8x1024
__device__ __align__(16) float g_h4[1638400];    // 100x4x4x1024
__device__ __align__(16) float g_part[20000000]; // split-K partials
__device__ __align__(16) float g_R[80000];
__device__ __align__(16) float g_tab[800];
__device__ __align__(16) float g_mean[4096];
__device__ __align__(16) float g_invstd[4096];
__device__ __align__(16) float g_bnsum[4096];
__device__ __align__(16) float g_bnss[4096];
__device__ __align__(16) float g_d0[921600];     // 100x3x3x1024 NHWC
__device__ __align__(16) float g_t1[1280000];    // 100x5x5x512
__device__ __align__(16) float g_t2[3097600];    // 100x11x11x256
__device__ __align__(16) float g_t3[6771200];    // 100x23x23x128
__device__ __align__(16) float g_t4[14137600];   // 100x47x47x64

// ---------------- helpers ----------------
__device__ __forceinline__ unsigned long long pack2(float v) {
    unsigned long long r; asm("mov.b64 %0, {%1, %1};" : "=l"(r) : "f"(v)); return r;
}
__device__ __forceinline__ void fma2(unsigned long long& a, unsigned long long x,
                                     unsigned long long y) {
    asm("fma.rn.f32x2 %0, %1, %2, %0;" : "+l"(a) : "l"(x), "l"(y));
}
__device__ __forceinline__ float2 unpack2(unsigned long long v) {
    float lo, hi; asm("mov.b64 {%0, %1}, %2;" : "=f"(lo), "=f"(hi) : "l"(v));
    return make_float2(lo, hi);
}
__device__ __forceinline__ int i4(const int4 v, int z) {
    return z == 0 ? v.x : z == 1 ? v.y : z == 2 ? v.z : v.w;
}
__device__ __forceinline__ unsigned t32(float f) {
    unsigned r; asm("cvt.rna.tf32.f32 %0, %1;" : "=r"(r) : "f"(f)); return r;
}
__device__ __forceinline__ float t32f(float f) {
    return __uint_as_float(t32(f));
}
__device__ __forceinline__ void mma8(float* c, const unsigned* a, const unsigned* b) {
    asm("mma.sync.aligned.m16n8k8.row.col.f32.tf32.tf32.f32 "
        "{%0,%1,%2,%3},{%4,%5,%6,%7},{%8,%9},{%0,%1,%2,%3};"
        : "+f"(c[0]), "+f"(c[1]), "+f"(c[2]), "+f"(c[3])
        : "r"(a[0]), "r"(a[1]), "r"(a[2]), "r"(a[3]), "r"(b[0]), "r"(b[1]));
}

// ---------------- GP ----------------
struct GP {
    const float *A, *B, *bias, *meanp, *ivsp; float* C;
    int M, N, K, lda, ldb, subM, bmode, sh;
    int CI, IH, IW, OW, OHW, s, pp, pd;
    int4 Mz, Kz, wOffz, HWpz, OWpz, pyz, pxz, ky0z, kx0z, nkxz;
    int OHfull, OWfull, CO, act;
};

// ---------------- tf32 MMA implicit GEMM (swizzled fragment-major A smem) -------
// AM=0: plain A[M,K](lda). AM=1: fwd-conv NHWC gather (mean-sub). AM=2: parity gather.
// EP=0: C[r*N+c]+bias. EP=1: split-K raw partial. EP=3: parity NHWC store + bias.
template<int BN, int AM, int EP>
__global__ void __launch_bounds__(256, 2) gemm_m(GP p)
{
    constexpr int BK = 16;
    constexpr int NWN = BN / 32;
    constexpr int NWM = 8 / NWN;
    constexpr int RW = 128 / NWM;
    constexpr int MT = RW / 16;
    constexpr int NVB = BN / 64;
    __shared__ __align__(16) float As[2][2][8][128];
    __shared__ __align__(16) float Bs[2][BK][BN + 8];
    const int tid = threadIdx.x;
    const int z = blockIdx.z;
    const int M = (AM == 2) ? i4(p.Mz, z) : p.M;
    const int K = (AM == 2) ? i4(p.Kz, z) : p.K;
    const int m0 = blockIdx.y * 128;
    if (m0 >= M) return;
    const int n0 = blockIdx.x * BN;
    const int koff = (EP == 1) ? z * K : 0;
    const int lane = tid & 31, wid = tid >> 5;
    const int warp_m = wid / NWN, warp_n = wid % NWN;
    const int g = lane >> 2, tig = lane & 3;

    int HWp = 0, OWp = 0, py = 0, px = 0, ky0 = 0, kx0 = 0, nkx = 1;
    if (AM == 2) {
        HWp = i4(p.HWpz, z); OWp = i4(p.OWpz, z); py = i4(p.pyz, z); px = i4(p.pxz, z);
        ky0 = i4(p.ky0z, z); kx0 = i4(p.kx0z, z); nkx = i4(p.nkxz, z);
    }
    const float* Bb = p.B + ((AM == 2) ? (size_t)i4(p.wOffz, z) : 0);

    const int lanoff = (tid & 3) << 2;
    const float* meanp_t = p.meanp + lanoff;
    const float* aptr[2];
    int amask[2];
    int ry = 0, rx = 0;
    if (AM == 2) { ry = (py + p.pd) & 1; rx = (px + p.pd) & 1; }
    if (AM >= 1) {
#pragma unroll
        for (int i = 0; i < 2; i++) {
            int r = (tid >> 2) + 64 * i;
            int gm = m0 + r;
            bool ok = gm < M;
            int gg = ok ? gm : 0;
            int msk = 0;
            if (AM == 1) {
                int b = gg / p.OHW, hw = gg - b * p.OHW;
                int oy = hw / p.OW, ox = hw - oy * p.OW;
                int ay = oy * p.s - p.pp, ax = ox * p.s - p.pp;
                if (ok) {
#pragma unroll
                    for (int tap = 0; tap < 9; tap++) {
                        int ky = tap / 3, kx = tap - 3 * (tap / 3);
                        if ((unsigned)(ay + ky) < (unsigned)p.IH &&
                            (unsigned)(ax + kx) < (unsigned)p.IW) msk |= 1 << tap;
                    }
                }
                aptr[i] = p.A + (long)b * p.IH * p.IW * p.CI +
                          (long)(ay * p.IW + ax) * p.CI + lanoff;
            } else {
                int b = gg / HWp, rr2 = gg - b * HWp;
                int ly = rr2 / OWp, lx = rr2 - ly * OWp;
                int aoy = py + 2 * ly - p.pd, aox = px + 2 * lx - p.pd;
                int nky = 2 - ky0;
                int ntc = nky * nkx;
                if (ok) {
                    for (int tt = 0; tt < ntc; tt++) {
                        int jy = (nkx == 2) ? (tt >> 1) : tt;
                        int jx = (nkx == 2) ? (tt & 1) : 0;
                        int ky = ky0 + 2 * jy, kx = kx0 + 2 * jx;
                        int tyy = aoy + ky, txx = aox + kx;
                        if (tyy >= 0 && txx >= 0 && (tyy >> 1) < p.IH && (txx >> 1) < p.IW)
                            msk |= 1 << tt;
                    }
                }
                int ey = (aoy - ry) >> 1, ex = (aox - rx) >> 1;
                aptr[i] = p.A + (long)b * p.IH * p.IW * p.CI +
                          (long)(ey * p.IW + ex) * p.CI + lanoff;
            }
            amask[i] = msk;
        }
    }

    const int NT = K / BK;
    float4 ra[2], rb[NVB];

    auto loadA = [&](int t) {
        const int k0 = koff + t * BK;
        if (AM == 0) {
#pragma unroll
            for (int i = 0; i < 2; i++) {
                int r = (tid >> 2) + 64 * i;
                int gm = m0 + r;
                float4 tmp = make_float4(0.f, 0.f, 0.f, 0.f);
                if (gm < M)
                    tmp = *(const float4*)(p.A + (size_t)gm * p.lda + k0 + lanoff);
                ra[i] = tmp;
            }
            return;
        }
        const int kr = k0 & (p.CI - 1);
        if (AM == 1) {
            int tap = k0 >> p.sh;
            int ky = tap / 3, kx = tap - 3 * ky;
            int dt = (ky * p.IW + kx) * p.CI + kr;
            const float4 mu = *(const float4*)(meanp_t + kr);
#pragma unroll
            for (int i = 0; i < 2; i++) {
                float4 tmp = make_float4(0.f, 0.f, 0.f, 0.f);
                if ((amask[i] >> tap) & 1) {
                    tmp = *(const float4*)(aptr[i] + dt);
                    tmp.x -= mu.x; tmp.y -= mu.y; tmp.z -= mu.z; tmp.w -= mu.w;
                }
                ra[i] = tmp;
            }
        } else {
            int tt = k0 >> p.sh;
            int jy, jx;
            if (nkx == 2) { jy = tt >> 1; jx = tt & 1; } else { jy = tt; jx = 0; }
            int dt = ((ry + jy) * p.IW + (rx + jx)) * p.CI + kr;
#pragma unroll
            for (int i = 0; i < 2; i++) {
                float4 tmp = make_float4(0.f, 0.f, 0.f, 0.f);
                if ((amask[i] >> tt) & 1)
                    tmp = *(const float4*)(aptr[i] + dt);
                ra[i] = tmp;
            }
        }
    };
    auto loadB = [&](int t) {
        const int k0 = koff + t * BK;
#pragma unroll
        for (int i = 0; i < NVB; i++) {
            int vid = tid + i * 256;
            int n4 = vid % (BN / 4), kc = vid / (BN / 4);
            rb[i] = *(const float4*)(Bb + (size_t)(k0 + kc) * p.ldb + n0 + n4 * 4);
        }
    };
    auto storeT = [&](int buf) {
#pragma unroll
        for (int i = 0; i < 2; i++) {
            int vid = tid + i * 256;
            int r = vid >> 2, kc = (vid & 3) << 2;
            int c = kc >> 3, h = (kc >> 2) & 1;
            int gi = r & 7;
            int s2 = (gi >> 1) & 3;
            float* tb = &As[buf][c][r >> 4][gi * 16 + ((r >> 3) & 1) + (h << 1)];
            tb[(0 ^ s2) * 4] = t32f(ra[i].x);
            tb[(1 ^ s2) * 4] = t32f(ra[i].y);
            tb[(2 ^ s2) * 4] = t32f(ra[i].z);
            tb[(3 ^ s2) * 4] = t32f(ra[i].w);
        }
#pragma unroll
        for (int i = 0; i < NVB; i++) {
            int vid = tid + i * 256;
            int n4 = vid % (BN / 4), kc = vid / (BN / 4);
            float4 cv = make_float4(t32f(rb[i].x), t32f(rb[i].y),
                                    t32f(rb[i].z), t32f(rb[i].w));
            *(float4*)&Bs[buf][kc][n4 * 4] = cv;
        }
    };

    float acc[MT][4][4];
#pragma unroll
    for (int mt = 0; mt < MT; mt++)
#pragma unroll
        for (int nt = 0; nt < 4; nt++)
#pragma unroll
            for (int r = 0; r < 4; r++) acc[mt][nt][r] = 0.f;

    loadA(0); loadB(0);
    storeT(0);
    __syncthreads();

    const int aoffs = g * 16 + ((tig ^ ((g >> 1) & 3)) << 2);

    for (int t = 0; t < NT; t++) {
        int cur = t & 1;
        if (t + 1 < NT) { loadA(t + 1); loadB(t + 1); }
#pragma unroll
        for (int c8 = 0; c8 < 2; c8++) {
            unsigned aF[MT][4], bF[4][2];
#pragma unroll
            for (int mt = 0; mt < MT; mt++) {
                const float4 av = *(const float4*)&As[cur][c8][warp_m * MT + mt][aoffs];
                aF[mt][0] = __float_as_uint(av.x);
                aF[mt][1] = __float_as_uint(av.y);
                aF[mt][2] = __float_as_uint(av.z);
                aF[mt][3] = __float_as_uint(av.w);
            }
#pragma unroll
            for (int nt = 0; nt < 4; nt++) {
                int nc = warp_n * 32 + nt * 8 + g;
                bF[nt][0] = __float_as_uint(Bs[cur][c8 * 8 + tig][nc]);
                bF[nt][1] = __float_as_uint(Bs[cur][c8 * 8 + tig + 4][nc]);
            }
#pragma unroll
            for (int mt = 0; mt < MT; mt++)
#pragma unroll
                for (int nt = 0; nt < 4; nt++)
                    mma8(acc[mt][nt], aF[mt], bF[nt]);
        }
        if (t + 1 < NT) storeT((t + 1) & 1);
        __syncthreads();
    }

#pragma unroll
    for (int mt = 0; mt < MT; mt++) {
#pragma unroll
        for (int half = 0; half < 2; half++) {
            int r = m0 + warp_m * RW + mt * 16 + g + 8 * half;
            if (r >= M) continue;
            if (EP == 1) {
                float* Cp = p.C + ((size_t)z * p.M + r) * p.N;
#pragma unroll
                for (int nt = 0; nt < 4; nt++) {
                    int c0 = n0 + warp_n * 32 + nt * 8 + 2 * tig;
                    *(float2*)(Cp + c0) = half
                        ? make_float2(acc[mt][nt][2], acc[mt][nt][3])
                        : make_float2(acc[mt][nt][0], acc[mt][nt][1]);
                }
            } else if (EP == 0) {
                float* Cp = p.C + (size_t)r * p.N;
#pragma unroll
                for (int nt = 0; nt < 4; nt++) {
                    int c0 = n0 + warp_n * 32 + nt * 8 + 2 * tig;
                    float2 bb = *(const float2*)(p.bias + c0);
                    float2 v = half
                        ? make_float2(acc[mt][nt][2], acc[mt][nt][3])
                        : make_float2(acc[mt][nt][0], acc[mt][nt][1]);
                    v.x += bb.x; v.y += bb.y;
                    *(float2*)(Cp + c0) = v;
                }
            } else {
                int b = r / HWp, rr = r - b * HWp;
                int ly = rr / OWp, lx = rr - ly * OWp;
                int oy = py + 2 * ly, ox = px + 2 * lx;
                size_t base = (((size_t)b * p.OHfull + oy) * p.OWfull + ox) * (size_t)p.CO;
#pragma unroll
                for (int nt = 0; nt < 4; nt++) {
                    int c0 = n0 + warp_n * 32 + nt * 8 + 2 * tig;
                    float2 bb = *(const float2*)(p.bias + c0);
                    float2 v = half
                        ? make_float2(acc[mt][nt][2], acc[mt][nt][3])
                        : make_float2(acc[mt][nt][0], acc[mt][nt][1]);
                    v.x += bb.x; v.y += bb.y;
                    *(float2*)(p.C + base + c0) = v;
                }
            }
        }
    }
}

// ---------------- fp32 GEMM (fc only) ----------------
template<int BM, int BN, int TM, int TN, int EP>
__global__ void __launch_bounds__(256, 2) gemm_u(GP p)
{
    constexpr int BK = 16;
    constexpr int NVA = (BM * BK) / 1024;
    constexpr int NVB = (BN * BK) / 1024;
    constexpr int TP = TM / 2;
    __shared__ __align__(16) float As[2][BK][BM + 4];
    __shared__ __align__(16) float Bs[2][BK][BN + 4];
    const int tid = threadIdx.x, tx = tid & 15, ty = tid >> 4;
    const int z = blockIdx.z;
    const int M = p.M, K = p.K;
    const int m0 = blockIdx.y * BM;
    if (m0 >= M) return;
    const int n0 = blockIdx.x * BN;
    const int koff = (EP == 1) ? z * K : 0;
    const int NT = K / BK;
    float4 ra[NVA], rb[NVB];
    const bool vecB = ((p.ldb & 3) == 0) && (n0 + BN <= p.N);

    auto loadA = [&](int t) {
        const int k0 = koff + t * BK;
#pragma unroll
        for (int i = 0; i < NVA; i++) {
            int vid = tid + i * 256;
            int r = vid >> 2, kc = (vid & 3) << 2;
            int gm = m0 + r;
            float4 v = make_float4(0.f, 0.f, 0.f, 0.f);
            if (gm < M) {
                v = *(const float4*)(p.A + (size_t)gm * p.lda + k0 + kc);
                if (p.subM) {
                    const float4 mu = *(const float4*)(p.meanp + ((k0 + kc) & 1023));
                    v.x -= mu.x; v.y -= mu.y; v.z -= mu.z; v.w -= mu.w;
                }
            }
            ra[i] = v;
        }
    };
    auto loadB = [&](int t) {
        const int k0 = koff + t * BK;
#pragma unroll
        for (int i = 0; i < NVB; i++) {
            int vid = tid + i * 256;
            int n4 = vid % (BN / 4), kc = vid / (BN / 4);
            int gk = k0 + kc;
            int row = (p.bmode == 2) ? (((gk & 1023) << 4) + (gk >> 10)) : gk;
            float4 v;
            if (vecB) {
                v = *(const float4*)(p.B + (size_t)row * p.ldb + n0 + n4 * 4);
            } else {
                float w[4];
#pragma unroll
                for (int j = 0; j < 4; j++) {
                    int gn = n0 + n4 * 4 + j;
                    w[j] = (gn < p.N) ? p.B[(size_t)row * p.ldb + gn] : 0.f;
                }
                v = make_float4(w[0], w[1], w[2], w[3]);
            }
            if (p.bmode == 2) {
                float s = p.ivsp[gk & 1023];
                v.x *= s; v.y *= s; v.z *= s; v.w *= s;
            }
            rb[i] = v;
        }
    };
    auto storeT = [&](int buf) {
#pragma unroll
        for (int i = 0; i < NVA; i++) {
            int vid = tid + i * 256;
            int r = vid >> 2, kc = (vid & 3) << 2;
            As[buf][kc + 0][r] = ra[i].x;
            As[buf][kc + 1][r] = ra[i].y;
            As[buf][kc + 2][r] = ra[i].z;
            As[buf][kc + 3][r] = ra[i].w;
        }
#pragma unroll
        for (int i = 0; i < NVB; i++) {
            int vid = tid + i * 256;
            int n4 = vid % (BN / 4), kc = vid / (BN / 4);
            *(float4*)&Bs[buf][kc][n4 * 4] = rb[i];
        }
    };

    unsigned long long acc2[TP][TN];
#pragma unroll
    for (int q = 0; q < TP; q++)
#pragma unroll
        for (int j = 0; j < TN; j++) acc2[q][j] = 0ull;

    loadA(0); loadB(0);
    storeT(0);
    __syncthreads();

    for (int t = 0; t < NT; t++) {
        int cur = t & 1;
        if (t + 1 < NT) { loadA(t + 1); loadB(t + 1); }
#pragma unroll
        for (int k = 0; k < BK; k++) {
            unsigned long long ap[TP];
#pragma unroll
            for (int g = 0; g < TM / 4; g++) {
                const ulonglong2 av = *(const ulonglong2*)&As[cur][k][g * 64 + tx * 4];
                ap[2 * g] = av.x; ap[2 * g + 1] = av.y;
            }
            unsigned long long bb[TN];
#pragma unroll
            for (int h = 0; h < TN / 4; h++) {
                const float4 b4 = *(const float4*)&Bs[cur][k][h * 64 + ty * 4];
                bb[4 * h + 0] = pack2(b4.x); bb[4 * h + 1] = pack2(b4.y);
                bb[4 * h + 2] = pack2(b4.z); bb[4 * h + 3] = pack2(b4.w);
            }
#pragma unroll
            for (int q = 0; q < TP; q++)
#pragma unroll
                for (int j = 0; j < TN; j++)
                    fma2(acc2[q][j], ap[q], bb[j]);
        }
        if (t + 1 < NT) storeT((t + 1) & 1);
        __syncthreads();
    }

#pragma unroll
    for (int q = 0; q < TP; q++) {
        float2 vv[TN];
#pragma unroll
        for (int j = 0; j < TN; j++) vv[j] = unpack2(acc2[q][j]);
#pragma unroll
        for (int e = 0; e < 2; e++) {
            int gm = m0 + (q >> 1) * 64 + (tx << 2) + ((q & 1) << 1) + e;
            if (gm >= M) continue;
            if (EP == 1) {
                float* Cp = p.C + ((size_t)z * p.M + gm) * p.N;
#pragma unroll
                for (int j = 0; j < TN; j++) {
                    int gn = n0 + (j >> 2) * 64 + (ty << 2) + (j & 3);
                    if (gn < p.N) Cp[gn] = e ? vv[j].y : vv[j].x;
                }
            } else {
                size_t base = (size_t)gm * p.N;
#pragma unroll
                for (int j = 0; j < TN; j++) {
                    int gn = n0 + (j >> 2) * 64 + (ty << 2) + (j & 3);
                    if (gn < p.N) p.C[base + gn] = (e ? vv[j].y : vv[j].x) + p.bias[gn];
                }
            }
        }
    }
}

// ---------------- aux kernels ----------------

__global__ void conv1_nhwc(const float* __restrict__ x, const float* __restrict__ w,
                           const float* __restrict__ b, float* __restrict__ h1) {
    if (blockIdx.x == 0 && blockIdx.y == 0) {
        for (int i = threadIdx.x; i < 4096; i += 128) { g_bnsum[i] = 0.f; g_bnss[i] = 0.f; }
    }
    int pix = blockIdx.x, img = blockIdx.y, co = threadIdx.x;
    int oy = pix >> 5, ox = pix & 31;
    __shared__ float xv[9];
    if (co < 9) {
        int ky = co / 3, kx = co % 3;
        int iy = 2 * oy - 1 + ky, ix = 2 * ox - 1 + kx;
        xv[co] = ((unsigned)iy < 64u && (unsigned)ix < 64u)
                     ? x[(size_t)img * 4096 + iy * 64 + ix] : 0.f;
    }
    __syncthreads();
    float acc = b[co];
#pragma unroll
    for (int t = 0; t < 9; t++) acc = fmaf(xv[t], w[co * 9 + t], acc);
    acc = (acc >= 0.f) ? acc : 0.01f * acc;
    h1[((size_t)img * 1024 + pix) * 128 + co] = acc;
}

__global__ void bn_part(const float* __restrict__ h, int C, long total, int L) {
    long stride = (long)gridDim.x * 256;
    long e = (long)blockIdx.x * 256 + threadIdx.x;
    if (e >= total) return;
    int c = (int)(e % C);
    float s = 0.f, ss = 0.f;
    for (; e < total; e += stride) { float v = h[e]; s += v; ss += v * v; }
    atomicAdd(&g_bnsum[L * 1024 + c], s);
    atomicAdd(&g_bnss[L * 1024 + c], ss);
}

__global__ void wt_fold(const float* __restrict__ w, float* __restrict__ wt,
                        int CI, int CO, int L, float cnt) {
    int c0 = blockIdx.x * 32, o0 = blockIdx.y * 32;
    __shared__ float tile[32][289];
    __shared__ float sig[32];
    int t = threadIdx.x;
    if (t < 32) {
        int ci = c0 + t;
        float m = g_bnsum[L * 1024 + ci] / cnt;
        float var = g_bnss[L * 1024 + ci] / cnt - m * m;
        float s = rsqrtf(var + 1e-5f);
        sig[t] = s;
        if (o0 == 0) { g_mean[L * 1024 + ci] = m; g_invstd[L * 1024 + ci] = s; }
    }
    __syncthreads();
    for (int i = t; i < 32 * 288; i += 256) {
        int r = i / 288, j = i - r * 288;
        tile[r][j] = w[((size_t)(o0 + r) * CI + c0) * 9 + j];
    }
    __syncthreads();
    for (int i = t; i < 288 * 32; i += 256) {
        int tt = i & 31, q = i >> 5;
        int cc = q / 9, tap = q - cc * 9;
        int k = tap * CI + c0 + cc;
        wt[(size_t)k * CO + o0 + tt] = tile[tt][cc * 9 + tap] * sig[cc];
    }
}

__global__ void bn_fin3(float cnt) {
    int c = blockIdx.x * 256 + threadIdx.x;
    if (c < 1024) {
        float m = g_bnsum[3072 + c] / cnt;
        float var = g_bnss[3072 + c] / cnt - m * m;
        g_mean[3072 + c] = m;
        g_invstd[3072 + c] = rsqrtf(var + 1e-5f);
    }
}

__global__ void wt_par(const float* __restrict__ w, float* __restrict__ wt,
                       int CI, int CO, int4 Ktz, int4 wOffz, int4 ky0z, int4 kx0z, int4 nkxz) {
    int z = blockIdx.z;
    int Kt = i4(Ktz, z);
    int idx = blockIdx.x * 256 + threadIdx.x;
    if (idx >= Kt * CO) return;
    int k = idx / CO, co = idx - k * CO;
    int ci = k % CI, tt = k / CI;
    int nkx = i4(nkxz, z);
    int jy, jx;
    if (nkx == 2) { jy = tt >> 1; jx = tt & 1; } else { jy = tt; jx = 0; }
    int ky = i4(ky0z, z) + 2 * jy, kx = i4(kx0z, z) + 2 * jx;
    wt[i4(wOffz, z) + idx] = w[(((size_t)ci * CO + co) * 3 + (2 - ky)) * 3 + (2 - kx)];
}

__global__ void perm_dec(const float* __restrict__ w, const float* __restrict__ b,
                         float* __restrict__ ow, float* __restrict__ ob) {
    long idx = (long)blockIdx.x * 256 + threadIdx.x;
    if (idx >= (long)800 * 9216) return;
    int k = (int)(idx / 9216), n = (int)(idx - (long)k * 9216);
    int hw = n >> 10, c = n & 1023;
    ow[idx] = w[(size_t)k * 9216 + c * 9 + hw];
    if (k == 0) ob[n] = b[c * 9 + hw];
}

__global__ void reduce_s(const float4* __restrict__ part, const float4* __restrict__ bias,
                         float4* __restrict__ out, int total4, int n4, int S) {
    int i = blockIdx.x * 256 + threadIdx.x;
    if (i >= total4) return;
    float4 s = part[i];
    for (int z = 1; z < S; z++) {
        float4 q = part[(size_t)z * total4 + i];
        s.x += q.x; s.y += q.y; s.z += q.z; s.w += q.w;
    }
    float4 b = bias[i % n4];
    s.x += b.x; s.y += b.y; s.z += b.z; s.w += b.w;
    s.x = (s.x >= 0.f) ? s.x : 0.01f * s.x;
    s.y = (s.y >= 0.f) ? s.y : 0.01f * s.y;
    s.z = (s.z >= 0.f) ? s.z : 0.01f * s.z;
    s.w = (s.w >= 0.f) ? s.w : 0.01f * s.w;
    out[i] = s;
}

__global__ void reduce_fc(const float* __restrict__ part, const float* __restrict__ bias,
                          float* __restrict__ out) {
    int idx = blockIdx.x * 256 + threadIdx.x;
    if (idx >= 80000) return;
    int n = idx % 800;
    float s = 0.f;
#pragma unroll
    for (int z = 0; z < 8; z++) s += part[(size_t)z * 80000 + idx];
    s += bias[n];
    out[idx] = fmaxf(s, 0.f);
}

__global__ void init_tab(float* tab) {
    int k = blockIdx.x * 256 + threadIdx.x;
    if (k < 800) tab[k] = (float)cos(2.0 * 3.141592653589793238462643 * (double)k / 800.0);
}
__global__ void compute_R(const float* __restrict__ eig, const float* __restrict__ tab,
                          float* __restrict__ R) {
    int b = blockIdx.x;
    __shared__ float s[800], t[800];
    for (int i = threadIdx.x; i < 800; i += 256) { s[i] = eig[b * 800 + i]; t[i] = tab[i]; }
    __syncthreads();
    for (int o = threadIdx.x; o < 800; o += 256) {
        int m = o >> 3, l = o & 7;
        float acc = 0.f;
        for (int q = 0; q < 800; q++) {
            int mp = q >> 3, lp = q & 7;
            int ph = (8 * m * mp + 100 * l * lp) % 800;
            acc += s[q] * t[ph];
        }
        R[b * 800 + o] = acc;
    }
}
__global__ void write_C(const float* __restrict__ R, float* __restrict__ C) {
    int b = blockIdx.y, i = blockIdx.x;
    __shared__ float r[800];
    const float inv = 0.035355339059327376f;
    for (int q = threadIdx.x; q < 800; q += 256) r[q] = R[b * 800 + q] * inv;
    __syncthreads();
    size_t base = ((size_t)b * 800 + i) * 800;
    for (int j = threadIdx.x; j < 800; j += 256)
        C[base + j] = r[(i - j + 800) % 800];
}

__global__ void ct5_nhwc(const float* __restrict__ t4, const float* __restrict__ w,
                         const float* __restrict__ bias, float* __restrict__ out) {
    __shared__ float ws[576];
    for (int i = threadIdx.x; i < 576; i += 128) {
        int tap = i >> 6, ci = i & 63;
        int ky = tap / 3, kx = tap % 3;
        ws[i] = w[ci * 9 + (2 - ky) * 3 + (2 - kx)];
    }
    __syncthreads();
    int b = blockIdx.y;
    int o = blockIdx.x * 128 + threadIdx.x;
    if (o >= 2401) return;
    int oy = o / 49, ox = o % 49;
    float acc = bias[0];
#pragma unroll
    for (int ky = 0; ky < 3; ky++) {
        int iy = oy + ky - 2;
        if ((unsigned)iy >= 47u) continue;
#pragma unroll
        for (int kx = 0; kx < 3; kx++) {
            int ix = ox + kx - 2;
            if ((unsigned)ix >= 47u) continue;
            const float4* p4 = (const float4*)(t4 + ((size_t)(b * 47 + iy) * 47 + ix) * 64);
            const float4* w4 = (const float4*)(ws + (ky * 3 + kx) * 64);
#pragma unroll
            for (int q = 0; q < 16; q++) {
                float4 v = p4[q], wv = w4[q];
                acc += v.x * wv.x + v.y * wv.y + v.z * wv.z + v.w * wv.w;
            }
        }
    }
    out[(size_t)b * 2401 + o] = acc;
}

// ---------------- host ----------------
static float* symaddr(const void* s) {
    void* p = nullptr; cudaGetSymbolAddress(&p, s); return (float*)p;
}
static int log2i(int v) { int s = 0; while ((1 << s) < v) s++; return s; }

struct PM { int4 Mz, Kz, wOff, HWpz, OWpz, pyz, pxz, ky0z, kx0z, nkxz; int maxM, maxKt; };
static PM pmeta(int B, int CI, int OH, int pd, int CO) {
    PM m{}; int Mv[4], Kv[4], wo[4], hwp[4], owp[4], pyv[4], pxv[4], k0v[4], kx0v[4], nkxv[4];
    int wacc = 0, i = 0; m.maxM = 0; m.maxKt = 0;
    for (int py = 0; py < 2; py++)
        for (int px = 0; px < 2; px++, i++) {
            int ky0 = ((pd - py) % 2 + 2) % 2, nky = 2 - ky0;
            int kx0 = ((pd - px) % 2 + 2) % 2, nkx = 2 - kx0;
            int OHp = (OH - py + 1) / 2, OWp = (OH - px + 1) / 2;
            int Kt = CI * nky * nkx, Mp = B * OHp * OWp;
            Mv[i] = Mp; Kv[i] = Kt; wo[i] = wacc;
            hwp[i] = OHp * OWp; owp[i] = OWp;
            pyv[i] = py; pxv[i] = px; k0v[i] = ky0; kx0v[i] = kx0; nkxv[i] = nkx;
            wacc += CO * Kt;
            if (Mp > m.maxM) m.maxM = Mp;
            if (Kt > m.maxKt) m.maxKt = Kt;
        }
    m.Mz = make_int4(Mv[0], Mv[1], Mv[2], Mv[3]);
    m.Kz = make_int4(Kv[0], Kv[1], Kv[2], Kv[3]);
    m.wOff = make_int4(wo[0], wo[1], wo[2], wo[3]);
    m.HWpz = make_int4(hwp[0], hwp[1], hwp[2], hwp[3]);
    m.OWpz = make_int4(owp[0], owp[1], owp[2], owp[3]);
    m.pyz = make_int4(pyv[0], pyv[1], pyv[2], pyv[3]);
    m.pxz = make_int4(pxv[0], pxv[1], pxv[2], pxv[3]);
    m.ky0z = make_int4(k0v[0], k0v[1], k0v[2], k0v[3]);
    m.kx0z = make_int4(kx0v[0], kx0v[1], kx0v[2], kx0v[3]);
    m.nkxz = make_int4(nkxv[0], nkxv[1], nkxv[2], nkxv[3]);
    return m;
}

static void conv_fwd_gemm(const float* in, const float* bias, float* outp,
                          int B, int CI, int CO, int IH, int OWo, int L, int splitK) {
    GP p{};
    p.A = in; p.B = symaddr(g_wT); p.bias = bias;
    p.meanp = symaddr(g_mean) + L * 1024;
    p.N = CO; p.ldb = CO; p.sh = log2i(CI);
    p.CI = CI; p.IH = IH; p.IW = IH; p.OW = OWo; p.OHW = OWo * OWo; p.s = 2; p.pp = 1;
    p.M = B * p.OHW;
    p.C = symaddr(g_part); p.K = 9 * CI / splitK;
    dim3 g(CO / 128, (p.M + 127) / 128, splitK);
    gemm_m<128, 1, 1><<<g, 256>>>(p);
    int total4 = p.M * CO / 4;
    reduce_s<<<(total4 + 255) / 256, 256>>>(
        (const float4*)symaddr(g_part), (const float4*)bias, (float4*)outp,
        total4, CO / 4, splitK);
}

static void convT_mma(const float* in, const float* wraw, const float* bias,
                      float* out, int B, int CI, int CO, int IH, int OH, int pd) {
    float* wT = symaddr(g_wT);
    PM m = pmeta(B, CI, OH, pd, CO);
    wt_par<<<dim3((m.maxKt * CO + 255) / 256, 1, 4), 256>>>(
        wraw, wT, CI, CO, m.Kz, m.wOff, m.ky0z, m.kx0z, m.nkxz);
    GP p{};
    p.A = in; p.B = wT; p.bias = bias; p.C = out;
    p.N = CO; p.ldb = CO; p.CI = CI; p.IH = IH; p.IW = IH; p.pd = pd;
    p.sh = log2i(CI);
    p.Mz = m.Mz; p.Kz = m.Kz; p.wOffz = m.wOff; p.HWpz = m.HWpz; p.OWpz = m.OWpz;
    p.pyz = m.pyz; p.pxz = m.pxz; p.ky0z = m.ky0z; p.kx0z = m.kx0z; p.nkxz = m.nkxz;
    p.OHfull = OH; p.OWfull = OH; p.CO = CO;
    if (CO >= 128) {
        dim3 g(CO / 128, (m.maxM + 127) / 128, 4);
        gemm_m<128, 2, 3><<<g, 256>>>(p);
    } else {
        dim3 g(CO / 64, (m.maxM + 127) / 128, 4);
        gemm_m<64, 2, 3><<<g, 256>>>(p);
    }
}

extern "C" void kernel_launch(void* const* d_in, const int* in_sizes, int n_in,
                              void* d_out, int out_size) {
    const float* x       = (const float*)d_in[0];
    const float* conv1_w = (const float*)d_in[1];
    const float* conv1_b = (const float*)d_in[2];
    const float* conv2_w = (const float*)d_in[3];
    const float* conv2_b = (const float*)d_in[4];
    const float* conv3_w = (const float*)d_in[5];
    const float* conv3_b = (const float*)d_in[6];
    const float* conv4_w = (const float*)d_in[7];
    const float* conv4_b = (const float*)d_in[8];
    const float* fc_w    = (const float*)d_in[9];
    const float* fc_b    = (const float*)d_in[10];
    const float* dec_w   = (const float*)d_in[11];
    const float* dec_b   = (const float*)d_in[12];
    const float* ct1_w   = (const float*)d_in[13];
    const float* ct1_b   = (const float*)d_in[14];
    const float* ct2_w   = (const float*)d_in[15];
    const float* ct2_b   = (const float*)d_in[16];
    const float* ct3_w   = (const float*)d_in[17];
    const float* ct3_b   = (const float*)d_in[18];
    const float* ct4_w   = (const float*)d_in[19];
    const float* ct4_b   = (const float*)d_in[20];
    const float* ct5_w   = (const float*)d_in[21];
    const float* ct5_b   = (const float*)d_in[22];

    float* out = (float*)d_out;
    float* out_d   = out;
    float* out_C   = out + 240100;
    float* out_eig = out + 240100 + 64000000;

    float* h1 = symaddr(g_h1);
    float* h2 = symaddr(g_h2);
    float* h3 = symaddr(g_h3);
    float* h4 = symaddr(g_h4);
    float* part = symaddr(g_part);
    float* wT = symaddr(g_wT);
    float* R  = symaddr(g_R);
    float* tab = symaddr(g_tab);
    float* d0 = symaddr(g_d0);
    float* t1 = symaddr(g_t1);
    float* t2 = symaddr(g_t2);
    float* t3 = symaddr(g_t3);
    float* t4 = symaddr(g_t4);
    float* biasP = symaddr(g_bias);
    const int B = 100;

    // encoder (NHWC, BN folded, tf32 mma + split-K)
    conv1_nhwc<<<dim3(1024, B), 128>>>(x, conv1_w, conv1_b, h1);                 // 1
    bn_part<<<1024, 256>>>(h1, 128, (long)13107200, 0);                          // 2
    wt_fold<<<dim3(4, 8), 256>>>(conv2_w, wT, 128, 256, 0, 102400.f);            // 3
    conv_fwd_gemm(h1, conv2_b, h2, B, 128, 256, 32, 16, 0, 3);                   // 4 profiled
    bn_part<<<1024, 256>>>(h2, 256, (long)6553600, 1);
    wt_fold<<<dim3(8, 32), 256>>>(conv3_w, wT, 256, 1024, 1, 25600.f);
    conv_fwd_gemm(h2, conv3_b, h3, B, 256, 1024, 16, 8, 1, 3);
    bn_part<<<1024, 256>>>(h3, 1024, (long)6553600, 2);
    wt_fold<<<dim3(32, 32), 256>>>(conv4_w, wT, 1024, 1024, 2, 6400.f);
    conv_fwd_gemm(h3, conv4_b, h4, B, 1024, 1024, 8, 4, 2, 12);
    bn_part<<<1024, 256>>>(h4, 1024, (long)1638400, 3);
    bn_fin3<<<4, 256>>>(1600.f);

    // fc: fp32, B = fc_w in-place row remap + invstd fold; mean subtract in A
    {
        GP p{};
        p.A = h4; p.B = fc_w; p.bias = fc_b; p.C = part;
        p.meanp = symaddr(g_mean) + 3072; p.subM = 1;
        p.ivsp = symaddr(g_invstd) + 3072; p.bmode = 2;
        p.M = 100; p.N = 800; p.K = 2048; p.lda = 16384; p.ldb = 800;
        dim3 g(13, 2, 8);
        gemm_u<64, 64, 4, 4, 1><<<g, 256>>>(p);
    }
    reduce_fc<<<(80000 + 255) / 256, 256>>>(part, fc_b, out_eig);

    // spectral
    init_tab<<<4, 256>>>(tab);
    compute_R<<<B, 256>>>(out_eig, tab, R);
    write_C<<<dim3(800, B), 256>>>(R, out_C);

    // dec -> d0 NHWC via tf32 mma (M=100 zero-padded to 128-row tile)
    perm_dec<<<(int)(((long)800 * 9216 + 255) / 256), 256>>>(dec_w, dec_b, wT, biasP);
    {
        GP p{};
        p.A = R; p.B = wT; p.bias = biasP; p.C = d0;
        p.M = 100; p.N = 9216; p.K = 800; p.lda = 800; p.ldb = 9216;
        dim3 g(72, 1, 1);
        gemm_m<128, 0, 0><<<g, 256>>>(p);
    }

    // decoder convT (tf32 mma)
    convT_mma(d0, ct1_w, ct1_b, t1, B, 1024, 512, 3, 5, 1);
    convT_mma(t1, ct2_w, ct2_b, t2, B, 512, 256, 5, 11, 2);
    convT_mma(t2, ct3_w, ct3_b, t3, B, 256, 128, 11, 23, 2);
    convT_mma(t3, ct4_w, ct4_b, t4, B, 128, 64, 23, 47, 2);
    ct5_nhwc<<<dim3((2401 + 127) / 128, B), 128>>>(t4, ct5_w, ct5_b, out_d);
}